// round 1
// baseline (speedup 1.0000x reference)
#include <cuda_runtime.h>

#define N_TOK 4096
#define NH 12
#define HD 64
#define DMODEL 768
#define QK_SCALE 0.125f

// Scratch (device globals: allocation-free per harness rules)
__device__ float g_qkv[(size_t)N_TOK * 3 * DMODEL];   // raw qkv
__device__ float g_q[(size_t)NH * N_TOK * HD];        // [h][n][d], rope'd + scaled
__device__ float g_k[(size_t)NH * N_TOK * HD];        // [h][n][d], rope'd
__device__ float g_v[(size_t)NH * N_TOK * HD];        // [h][n][d]
__device__ float g_att[(size_t)N_TOK * DMODEL];       // attention output [n][h*HD+d]

// ---------------------------------------------------------------------------
// SGEMM: C[M,Nc] = A[M,K] @ B[K,Nc] + bias[Nc]
// 128x128 block tile, BK=8, 256 threads, 8x8 per thread. All dims divide.
// ---------------------------------------------------------------------------
__global__ void __launch_bounds__(256) sgemm_bias(
    const float* __restrict__ A, const float* __restrict__ B,
    const float* __restrict__ bias, float* __restrict__ C,
    int M, int Nc, int K)
{
    __shared__ float As[8][128];   // transposed A tile
    __shared__ float Bs[8][128];

    const int tid = threadIdx.x;
    const int tx = tid & 15, ty = tid >> 4;
    const int bx = blockIdx.x, by = blockIdx.y;

    const int a_row = tid >> 1;          // 0..127
    const int a_col = (tid & 1) * 4;     // 0 or 4
    const int b_row = tid >> 5;          // 0..7
    const int b_col = (tid & 31) * 4;    // 0..124

    const float* Ag = A + (size_t)(by * 128) * K;
    const float* Bg = B + bx * 128;

    float acc[8][8];
#pragma unroll
    for (int i = 0; i < 8; i++)
#pragma unroll
        for (int j = 0; j < 8; j++) acc[i][j] = 0.f;

    for (int k0 = 0; k0 < K; k0 += 8) {
        float4 av = *(const float4*)(Ag + (size_t)a_row * K + k0 + a_col);
        As[a_col + 0][a_row] = av.x;
        As[a_col + 1][a_row] = av.y;
        As[a_col + 2][a_row] = av.z;
        As[a_col + 3][a_row] = av.w;
        float4 bv = *(const float4*)(Bg + (size_t)(k0 + b_row) * Nc + b_col);
        *(float4*)&Bs[b_row][b_col] = bv;
        __syncthreads();
#pragma unroll
        for (int kk = 0; kk < 8; kk++) {
            float a[8], b[8];
            *(float4*)&a[0] = *(float4*)&As[kk][ty * 8];
            *(float4*)&a[4] = *(float4*)&As[kk][ty * 8 + 4];
            *(float4*)&b[0] = *(float4*)&Bs[kk][tx * 8];
            *(float4*)&b[4] = *(float4*)&Bs[kk][tx * 8 + 4];
#pragma unroll
            for (int i = 0; i < 8; i++)
#pragma unroll
                for (int j = 0; j < 8; j++)
                    acc[i][j] = fmaf(a[i], b[j], acc[i][j]);
        }
        __syncthreads();
    }

    const int row0 = by * 128 + ty * 8;
    const int col0 = bx * 128 + tx * 8;
    float bb[8];
    *(float4*)&bb[0] = *(const float4*)(bias + col0);
    *(float4*)&bb[4] = *(const float4*)(bias + col0 + 4);
#pragma unroll
    for (int i = 0; i < 8; i++) {
        float4 v0 = make_float4(acc[i][0] + bb[0], acc[i][1] + bb[1],
                                acc[i][2] + bb[2], acc[i][3] + bb[3]);
        float4 v1 = make_float4(acc[i][4] + bb[4], acc[i][5] + bb[5],
                                acc[i][6] + bb[6], acc[i][7] + bb[7]);
        *(float4*)(C + (size_t)(row0 + i) * Nc + col0) = v0;
        *(float4*)(C + (size_t)(row0 + i) * Nc + col0 + 4) = v1;
    }
}

// ---------------------------------------------------------------------------
// RoPE + scale + split into [h][n][d] layout
// ---------------------------------------------------------------------------
__global__ void __launch_bounds__(256) rope_split(const float* __restrict__ cosp,
                                                  const float* __restrict__ sinp)
{
    int idx = blockIdx.x * 256 + threadIdx.x;
    if (idx >= N_TOK * NH * HD) return;
    int d = idx & 63;
    int h = (idx >> 6) % NH;
    int n = idx / (NH * HD);

    float c = cosp[n * HD + d];
    float s = sinp[n * HD + d];
    const float* base = g_qkv + (size_t)n * (3 * DMODEL) + h * HD;
    float qv = base[d];
    float kv = base[DMODEL + d];
    float vv = base[2 * DMODEL + d];
    int dp = (d < 32) ? d + 32 : d - 32;
    float sgn = (d < 32) ? -1.f : 1.f;
    float qr = sgn * base[dp];
    float kr = sgn * base[DMODEL + dp];

    size_t o = ((size_t)h * N_TOK + n) * HD + d;
    g_q[o] = (qv * c + qr * s) * QK_SCALE;
    g_k[o] = kv * c + kr * s;
    g_v[o] = vv;
}

// ---------------------------------------------------------------------------
// Flash attention: grid (N/128, H), 256 threads.
// Per block: 128 queries, loop over 128-key tiles.
// S tile 128x128 (8x8/thread), online softmax (16-lane shfl), PV via smem P^T.
// ---------------------------------------------------------------------------
#define QT_S 132   // padded stride for transposed Q/K tiles (conflict-free + 16B aligned)
#define PS_S 132   // padded stride for P^T

__global__ void __launch_bounds__(256) attn_kernel()
{
    extern __shared__ float sm[];
    float* Qt = sm;                      // [64][QT_S]   Q^T: Qt[d][row]
    float* Kt = Qt + 64 * QT_S;          // [64][QT_S]   K^T: Kt[d][key]
    float* Vs = Kt + 64 * QT_S;          // [128][64]    V:  Vs[key][d]
    float* Ps = Vs + 128 * 64;           // [128][PS_S]  P^T: Ps[key][row]

    const int h = blockIdx.y;
    const int qb = blockIdx.x;
    const int tid = threadIdx.x;
    const int tx = tid & 15, ty = tid >> 4;

    const float* qg = g_q + ((size_t)h * N_TOK + (size_t)qb * 128) * HD;
    const float* kg = g_k + (size_t)h * N_TOK * HD;
    const float* vg = g_v + (size_t)h * N_TOK * HD;

    for (int idx = tid; idx < 128 * 64; idx += 256) {
        int r = idx >> 6, d = idx & 63;
        Qt[d * QT_S + r] = qg[idx];
    }

    float o[8][4];
    float m_i[8], l_i[8];
#pragma unroll
    for (int i = 0; i < 8; i++) {
        m_i[i] = -1e30f; l_i[i] = 0.f;
        o[i][0] = o[i][1] = o[i][2] = o[i][3] = 0.f;
    }

    for (int t = 0; t < N_TOK / 128; t++) {
        __syncthreads();   // previous tile's readers done before overwrite
        const float* kgt = kg + (size_t)t * 128 * HD;
        const float* vgt = vg + (size_t)t * 128 * HD;
        for (int idx = tid; idx < 128 * 64; idx += 256) {
            int r = idx >> 6, d = idx & 63;
            Kt[d * QT_S + r] = kgt[idx];
            Vs[idx] = vgt[idx];
        }
        __syncthreads();

        // S = Q K^T  (q pre-scaled)
        float s[8][8];
#pragma unroll
        for (int i = 0; i < 8; i++)
#pragma unroll
            for (int j = 0; j < 8; j++) s[i][j] = 0.f;

#pragma unroll 4
        for (int kk = 0; kk < 64; kk++) {
            float a[8], b[8];
            *(float4*)&a[0] = *(float4*)&Qt[kk * QT_S + ty * 8];
            *(float4*)&a[4] = *(float4*)&Qt[kk * QT_S + ty * 8 + 4];
            *(float4*)&b[0] = *(float4*)&Kt[kk * QT_S + tx * 8];
            *(float4*)&b[4] = *(float4*)&Kt[kk * QT_S + tx * 8 + 4];
#pragma unroll
            for (int i = 0; i < 8; i++)
#pragma unroll
                for (int j = 0; j < 8; j++)
                    s[i][j] = fmaf(a[i], b[j], s[i][j]);
        }

        // online softmax; rows owned by (ty, i); reduce over 16 tx lanes
#pragma unroll
        for (int i = 0; i < 8; i++) {
            float mt = s[i][0];
#pragma unroll
            for (int j = 1; j < 8; j++) mt = fmaxf(mt, s[i][j]);
#pragma unroll
            for (int off = 1; off < 16; off <<= 1)
                mt = fmaxf(mt, __shfl_xor_sync(0xffffffffu, mt, off));
            float mn = fmaxf(m_i[i], mt);
            float alpha = __expf(m_i[i] - mn);
            m_i[i] = mn;
            float rs = 0.f;
#pragma unroll
            for (int j = 0; j < 8; j++) {
                s[i][j] = __expf(s[i][j] - mn);
                rs += s[i][j];
            }
#pragma unroll
            for (int off = 1; off < 16; off <<= 1)
                rs += __shfl_xor_sync(0xffffffffu, rs, off);
            l_i[i] = l_i[i] * alpha + rs;
            o[i][0] *= alpha; o[i][1] *= alpha; o[i][2] *= alpha; o[i][3] *= alpha;
        }

        // stage P^T to smem
#pragma unroll
        for (int j = 0; j < 8; j++)
#pragma unroll
            for (int i = 0; i < 8; i++)
                Ps[(tx * 8 + j) * PS_S + ty * 8 + i] = s[i][j];
        __syncthreads();

        // O += P V
#pragma unroll 2
        for (int j = 0; j < 128; j++) {
            float a[8];
            *(float4*)&a[0] = *(float4*)&Ps[j * PS_S + ty * 8];
            *(float4*)&a[4] = *(float4*)&Ps[j * PS_S + ty * 8 + 4];
            float4 bv = *(const float4*)&Vs[j * 64 + tx * 4];
#pragma unroll
            for (int i = 0; i < 8; i++) {
                o[i][0] = fmaf(a[i], bv.x, o[i][0]);
                o[i][1] = fmaf(a[i], bv.y, o[i][1]);
                o[i][2] = fmaf(a[i], bv.z, o[i][2]);
                o[i][3] = fmaf(a[i], bv.w, o[i][3]);
            }
        }
    }

    // normalize + write [n][h*HD+d]
#pragma unroll
    for (int i = 0; i < 8; i++) {
        float inv = 1.f / l_i[i];
        int row = qb * 128 + ty * 8 + i;
        float4 v = make_float4(o[i][0] * inv, o[i][1] * inv,
                               o[i][2] * inv, o[i][3] * inv);
        *(float4*)(g_att + (size_t)row * DMODEL + h * HD + tx * 4) = v;
    }
}

// ---------------------------------------------------------------------------
extern "C" void kernel_launch(void* const* d_in, const int* in_sizes, int n_in,
                              void* d_out, int out_size)
{
    (void)in_sizes; (void)n_in; (void)out_size;
    const float* hs     = (const float*)d_in[0];
    const float* cosp   = (const float*)d_in[1];
    const float* sinp   = (const float*)d_in[2];
    const float* qkv_w  = (const float*)d_in[3];
    const float* qkv_b  = (const float*)d_in[4];
    const float* proj_w = (const float*)d_in[5];
    const float* proj_b = (const float*)d_in[6];
    float* out = (float*)d_out;

    void *p_qkv = nullptr, *p_att = nullptr;
    cudaGetSymbolAddress(&p_qkv, g_qkv);
    cudaGetSymbolAddress(&p_att, g_att);

    const int attn_smem = (64 * QT_S + 64 * QT_S + 128 * 64 + 128 * PS_S) * (int)sizeof(float);
    cudaFuncSetAttribute(attn_kernel, cudaFuncAttributeMaxDynamicSharedMemorySize, attn_smem);

    // 1) QKV = hs @ qkv_w + qkv_b
    sgemm_bias<<<dim3(3 * DMODEL / 128, N_TOK / 128), 256>>>(
        hs, qkv_w, qkv_b, (float*)p_qkv, N_TOK, 3 * DMODEL, DMODEL);

    // 2) RoPE + scale + split to [h][n][d]
    rope_split<<<(N_TOK * NH * HD + 255) / 256, 256>>>(cosp, sinp);

    // 3) Flash attention
    attn_kernel<<<dim3(N_TOK / 128, NH), 256, attn_smem>>>();

    // 4) out = att @ proj_w + proj_b
    sgemm_bias<<<dim3(DMODEL / 128, N_TOK / 128), 256>>>(
        (const float*)p_att, proj_w, proj_b, out, N_TOK, DMODEL, DMODEL);
}

// round 2
// speedup vs baseline: 2.7970x; 2.7970x over previous
#include <cuda_runtime.h>
#include <cstdint>

#define N_TOK 4096
#define NH 12
#define HD 64
#define DMODEL 768
#define QK_SCALE 0.125f

// Scratch (device globals: allocation-free per harness rules)
__device__ float g_qkv[(size_t)N_TOK * 3 * DMODEL];   // raw qkv (fp32)
__device__ float g_q[(size_t)NH * N_TOK * HD];        // [h][n][d], rope'd+scaled, tf32-rounded
__device__ float g_k[(size_t)NH * N_TOK * HD];        // [h][n][d], rope'd, tf32-rounded
__device__ float g_v[(size_t)NH * N_TOK * HD];        // [h][n][d], tf32-rounded
__device__ float g_att[(size_t)N_TOK * DMODEL];       // attention output [n][h*HD+d] (fp32)

// ---------------------------------------------------------------------------
// tf32 helpers
// ---------------------------------------------------------------------------
__device__ __forceinline__ uint32_t f2tf(float f) {
    uint32_t u;
    asm("cvt.rna.tf32.f32 %0, %1;" : "=r"(u) : "f"(f));
    return u;
}

__device__ __forceinline__ void mma_tf32(float& c0, float& c1, float& c2, float& c3,
                                         uint32_t a0, uint32_t a1, uint32_t a2, uint32_t a3,
                                         uint32_t b0, uint32_t b1) {
    asm volatile(
        "mma.sync.aligned.m16n8k8.row.col.f32.tf32.tf32.f32 "
        "{%0,%1,%2,%3}, {%4,%5,%6,%7}, {%8,%9}, {%0,%1,%2,%3};\n"
        : "+f"(c0), "+f"(c1), "+f"(c2), "+f"(c3)
        : "r"(a0), "r"(a1), "r"(a2), "r"(a3), "r"(b0), "r"(b1));
}

// ---------------------------------------------------------------------------
// tf32 GEMM: C[M,Nc] = A[M,K] @ B[K,Nc] + bias.  128x128x32 tiles, 256 thr.
// Warp grid 2x4, warp tile 64x32 (4 m-tiles x 4 n-tiles of m16n8k8).
// ---------------------------------------------------------------------------
#define AS_S 36    // (4r+k)%32 distinct for frag loads
#define BS_S 136   // 136%32==8 -> (8k+n)%32 distinct

__global__ void __launch_bounds__(256) gemm_tf32(
    const float* __restrict__ A, const float* __restrict__ B,
    const float* __restrict__ bias, float* __restrict__ C,
    int M, int Nc, int K)
{
    __shared__ uint32_t As[128 * AS_S];   // [row][k]
    __shared__ uint32_t Bs[32 * BS_S];    // [k][n]

    const int tid = threadIdx.x;
    const int lane = tid & 31;
    const int w = tid >> 5;
    const int wm = w >> 2, wn = w & 3;
    const int bx = blockIdx.x, by = blockIdx.y;

    const float* Ag = A + (size_t)(by * 128) * K;
    const float* Bg = B + bx * 128;

    float acc[4][4][4];
#pragma unroll
    for (int mt = 0; mt < 4; mt++)
#pragma unroll
        for (int nt = 0; nt < 4; nt++)
#pragma unroll
            for (int c = 0; c < 4; c++) acc[mt][nt][c] = 0.f;

    for (int k0 = 0; k0 < K; k0 += 32) {
        // fill A tile 128x32 (1024 float4)
#pragma unroll
        for (int i = 0; i < 4; i++) {
            int id = tid + i * 256;
            int r = id >> 3, c = (id & 7) * 4;
            float4 v = *(const float4*)(Ag + (size_t)r * K + k0 + c);
            uint4 u = make_uint4(f2tf(v.x), f2tf(v.y), f2tf(v.z), f2tf(v.w));
            *(uint4*)&As[r * AS_S + c] = u;
        }
        // fill B tile 32x128 (1024 float4)
#pragma unroll
        for (int i = 0; i < 4; i++) {
            int id = tid + i * 256;
            int r = id >> 5, c = (id & 31) * 4;
            float4 v = *(const float4*)(Bg + (size_t)(k0 + r) * Nc + c);
            uint4 u = make_uint4(f2tf(v.x), f2tf(v.y), f2tf(v.z), f2tf(v.w));
            *(uint4*)&Bs[r * BS_S + c] = u;
        }
        __syncthreads();

#pragma unroll
        for (int ks = 0; ks < 4; ks++) {
            const int kk = ks * 8 + (lane & 3);
            uint32_t a[4][4], b[4][2];
#pragma unroll
            for (int mt = 0; mt < 4; mt++) {
                int r = wm * 64 + mt * 16 + (lane >> 2);
                a[mt][0] = As[r * AS_S + kk];
                a[mt][1] = As[(r + 8) * AS_S + kk];
                a[mt][2] = As[r * AS_S + kk + 4];
                a[mt][3] = As[(r + 8) * AS_S + kk + 4];
            }
#pragma unroll
            for (int nt = 0; nt < 4; nt++) {
                int cn = wn * 32 + nt * 8 + (lane >> 2);
                b[nt][0] = Bs[kk * BS_S + cn];
                b[nt][1] = Bs[(kk + 4) * BS_S + cn];
            }
#pragma unroll
            for (int mt = 0; mt < 4; mt++)
#pragma unroll
                for (int nt = 0; nt < 4; nt++)
                    mma_tf32(acc[mt][nt][0], acc[mt][nt][1], acc[mt][nt][2], acc[mt][nt][3],
                             a[mt][0], a[mt][1], a[mt][2], a[mt][3],
                             b[nt][0], b[nt][1]);
        }
        __syncthreads();
    }

#pragma unroll
    for (int mt = 0; mt < 4; mt++) {
#pragma unroll
        for (int nt = 0; nt < 4; nt++) {
            int r = by * 128 + wm * 64 + mt * 16 + (lane >> 2);
            int cn = bx * 128 + wn * 32 + nt * 8 + 2 * (lane & 3);
            float b0 = bias[cn], b1 = bias[cn + 1];
            float2 v0 = make_float2(acc[mt][nt][0] + b0, acc[mt][nt][1] + b1);
            float2 v1 = make_float2(acc[mt][nt][2] + b0, acc[mt][nt][3] + b1);
            *(float2*)(C + (size_t)r * Nc + cn) = v0;
            *(float2*)(C + (size_t)(r + 8) * Nc + cn) = v1;
        }
    }
}

// ---------------------------------------------------------------------------
// RoPE + scale + split into [h][n][d] layout, tf32-rounded outputs
// ---------------------------------------------------------------------------
__global__ void __launch_bounds__(256) rope_split(const float* __restrict__ cosp,
                                                  const float* __restrict__ sinp)
{
    int idx = blockIdx.x * 256 + threadIdx.x;
    if (idx >= N_TOK * NH * HD) return;
    int d = idx & 63;
    int h = (idx >> 6) % NH;
    int n = idx / (NH * HD);

    float c = cosp[n * HD + d];
    float s = sinp[n * HD + d];
    const float* base = g_qkv + (size_t)n * (3 * DMODEL) + h * HD;
    float qv = base[d];
    float kv = base[DMODEL + d];
    float vv = base[2 * DMODEL + d];
    int dp = (d < 32) ? d + 32 : d - 32;
    float sgn = (d < 32) ? -1.f : 1.f;
    float qr = sgn * base[dp];
    float kr = sgn * base[DMODEL + dp];

    size_t o = ((size_t)h * N_TOK + n) * HD + d;
    g_q[o] = __uint_as_float(f2tf((qv * c + qr * s) * QK_SCALE));
    g_k[o] = __uint_as_float(f2tf(kv * c + kr * s));
    g_v[o] = __uint_as_float(f2tf(vv));
}

// ---------------------------------------------------------------------------
// Flash attention with tf32 mma.
// Grid (N/128, H), 256 threads = 8 warps; warp w owns query rows 16w..16w+15.
// Per 128-key tile: S = Q K^T (16 n-tiles), warp-local online softmax,
// P re-staged via warp-private smem rows, O += P V (8 n-tiles over d).
// ---------------------------------------------------------------------------
#define QS_S 68    // Qs/Ks stride: (4r+k)%32 = lane -> conflict-free
#define VS_S 72    // 72%32==8 -> (8k+d)%32 distinct for V B-frags
#define PP_S 132   // (4q+k)%32 distinct for P A-frags

__global__ void __launch_bounds__(256) attn_mma()
{
    extern __shared__ uint32_t sm[];
    uint32_t* Qs = sm;                    // [128][QS_S]
    uint32_t* Ks = Qs + 128 * QS_S;       // [128][QS_S]
    uint32_t* Vs = Ks + 128 * QS_S;       // [128][VS_S]
    uint32_t* Ps = Vs + 128 * VS_S;       // [128][PP_S]

    const int h = blockIdx.y;
    const int qb = blockIdx.x;
    const int tid = threadIdx.x;
    const int lane = tid & 31;
    const int w = tid >> 5;

    const float* qg = g_q + ((size_t)h * N_TOK + (size_t)qb * 128) * HD;
    const float* kg = g_k + (size_t)h * N_TOK * HD;
    const float* vg = g_v + (size_t)h * N_TOK * HD;

    // load Q tile (already tf32-rounded)
#pragma unroll
    for (int i = 0; i < 8; i++) {
        int id = tid + i * 256;
        int r = id >> 4, c = (id & 15) * 4;
        float4 v = *(const float4*)(qg + r * HD + c);
        *(uint4*)&Qs[r * QS_S + c] = make_uint4(
            __float_as_uint(v.x), __float_as_uint(v.y),
            __float_as_uint(v.z), __float_as_uint(v.w));
    }

    float o[8][4];
#pragma unroll
    for (int nt = 0; nt < 8; nt++)
#pragma unroll
        for (int c = 0; c < 4; c++) o[nt][c] = 0.f;
    float m0 = -1e30f, m1 = -1e30f, l0 = 0.f, l1 = 0.f;

    const int qrow = w * 16 + (lane >> 2);

    for (int t = 0; t < N_TOK / 128; t++) {
        __syncthreads();
        const float* kt = kg + (size_t)t * 128 * HD;
        const float* vt = vg + (size_t)t * 128 * HD;
#pragma unroll
        for (int i = 0; i < 8; i++) {
            int id = tid + i * 256;
            int r = id >> 4, c = (id & 15) * 4;
            float4 kv = *(const float4*)(kt + r * HD + c);
            float4 vv = *(const float4*)(vt + r * HD + c);
            *(uint4*)&Ks[r * QS_S + c] = make_uint4(
                __float_as_uint(kv.x), __float_as_uint(kv.y),
                __float_as_uint(kv.z), __float_as_uint(kv.w));
            *(uint4*)&Vs[r * VS_S + c] = make_uint4(
                __float_as_uint(vv.x), __float_as_uint(vv.y),
                __float_as_uint(vv.z), __float_as_uint(vv.w));
        }
        __syncthreads();

        // ---- S = Q K^T : 16 n-tiles over 128 keys
        float s[16][4];
#pragma unroll
        for (int nt = 0; nt < 16; nt++)
#pragma unroll
            for (int c = 0; c < 4; c++) s[nt][c] = 0.f;

#pragma unroll
        for (int ks = 0; ks < 8; ks++) {
            const int kk = ks * 8 + (lane & 3);
            uint32_t a0 = Qs[qrow * QS_S + kk];
            uint32_t a1 = Qs[(qrow + 8) * QS_S + kk];
            uint32_t a2 = Qs[qrow * QS_S + kk + 4];
            uint32_t a3 = Qs[(qrow + 8) * QS_S + kk + 4];
#pragma unroll
            for (int nt = 0; nt < 16; nt++) {
                int nn = nt * 8 + (lane >> 2);
                uint32_t b0 = Ks[nn * QS_S + kk];
                uint32_t b1 = Ks[nn * QS_S + kk + 4];
                mma_tf32(s[nt][0], s[nt][1], s[nt][2], s[nt][3],
                         a0, a1, a2, a3, b0, b1);
            }
        }

        // ---- online softmax (warp-local; rows qrow and qrow+8)
        // row 0 uses regs [0],[1]; row 1 uses [2],[3]
        {
            float mt = -1e30f;
#pragma unroll
            for (int nt = 0; nt < 16; nt++)
                mt = fmaxf(mt, fmaxf(s[nt][0], s[nt][1]));
            mt = fmaxf(mt, __shfl_xor_sync(0xffffffffu, mt, 1));
            mt = fmaxf(mt, __shfl_xor_sync(0xffffffffu, mt, 2));
            float nm = fmaxf(m0, mt);
            float al = __expf(m0 - nm);
            m0 = nm;
            float rs = 0.f;
#pragma unroll
            for (int nt = 0; nt < 16; nt++) {
                s[nt][0] = __expf(s[nt][0] - nm);
                s[nt][1] = __expf(s[nt][1] - nm);
                rs += s[nt][0] + s[nt][1];
            }
            rs += __shfl_xor_sync(0xffffffffu, rs, 1);
            rs += __shfl_xor_sync(0xffffffffu, rs, 2);
            l0 = l0 * al + rs;
#pragma unroll
            for (int nt = 0; nt < 8; nt++) { o[nt][0] *= al; o[nt][1] *= al; }
        }
        {
            float mt = -1e30f;
#pragma unroll
            for (int nt = 0; nt < 16; nt++)
                mt = fmaxf(mt, fmaxf(s[nt][2], s[nt][3]));
            mt = fmaxf(mt, __shfl_xor_sync(0xffffffffu, mt, 1));
            mt = fmaxf(mt, __shfl_xor_sync(0xffffffffu, mt, 2));
            float nm = fmaxf(m1, mt);
            float al = __expf(m1 - nm);
            m1 = nm;
            float rs = 0.f;
#pragma unroll
            for (int nt = 0; nt < 16; nt++) {
                s[nt][2] = __expf(s[nt][2] - nm);
                s[nt][3] = __expf(s[nt][3] - nm);
                rs += s[nt][2] + s[nt][3];
            }
            rs += __shfl_xor_sync(0xffffffffu, rs, 1);
            rs += __shfl_xor_sync(0xffffffffu, rs, 2);
            l1 = l1 * al + rs;
#pragma unroll
            for (int nt = 0; nt < 8; nt++) { o[nt][2] *= al; o[nt][3] *= al; }
        }

        // ---- stage P (tf32) into warp-private smem rows
#pragma unroll
        for (int nt = 0; nt < 16; nt++) {
            int col = nt * 8 + 2 * (lane & 3);
            uint2 p0 = make_uint2(f2tf(s[nt][0]), f2tf(s[nt][1]));
            uint2 p1 = make_uint2(f2tf(s[nt][2]), f2tf(s[nt][3]));
            *(uint2*)&Ps[qrow * PP_S + col] = p0;
            *(uint2*)&Ps[(qrow + 8) * PP_S + col] = p1;
        }
        __syncwarp();

        // ---- O += P V : k over 128 keys (16 k-steps), 8 d-tiles
#pragma unroll
        for (int ks = 0; ks < 16; ks++) {
            const int kk = ks * 8 + (lane & 3);
            uint32_t a0 = Ps[qrow * PP_S + kk];
            uint32_t a1 = Ps[(qrow + 8) * PP_S + kk];
            uint32_t a2 = Ps[qrow * PP_S + kk + 4];
            uint32_t a3 = Ps[(qrow + 8) * PP_S + kk + 4];
#pragma unroll
            for (int nt = 0; nt < 8; nt++) {
                int dd = nt * 8 + (lane >> 2);
                uint32_t b0 = Vs[kk * VS_S + dd];
                uint32_t b1 = Vs[(kk + 4) * VS_S + dd];
                mma_tf32(o[nt][0], o[nt][1], o[nt][2], o[nt][3],
                         a0, a1, a2, a3, b0, b1);
            }
        }
        __syncwarp();
    }

    // ---- normalize + write [n][h*HD+d]
    float inv0 = 1.f / l0, inv1 = 1.f / l1;
    int row0 = qb * 128 + qrow;
#pragma unroll
    for (int nt = 0; nt < 8; nt++) {
        int dd = h * HD + nt * 8 + 2 * (lane & 3);
        float2 v0 = make_float2(o[nt][0] * inv0, o[nt][1] * inv0);
        float2 v1 = make_float2(o[nt][2] * inv1, o[nt][3] * inv1);
        *(float2*)(g_att + (size_t)row0 * DMODEL + dd) = v0;
        *(float2*)(g_att + (size_t)(row0 + 8) * DMODEL + dd) = v1;
    }
}

// ---------------------------------------------------------------------------
extern "C" void kernel_launch(void* const* d_in, const int* in_sizes, int n_in,
                              void* d_out, int out_size)
{
    (void)in_sizes; (void)n_in; (void)out_size;
    const float* hs     = (const float*)d_in[0];
    const float* cosp   = (const float*)d_in[1];
    const float* sinp   = (const float*)d_in[2];
    const float* qkv_w  = (const float*)d_in[3];
    const float* qkv_b  = (const float*)d_in[4];
    const float* proj_w = (const float*)d_in[5];
    const float* proj_b = (const float*)d_in[6];
    float* out = (float*)d_out;

    void *p_qkv = nullptr, *p_att = nullptr;
    cudaGetSymbolAddress(&p_qkv, g_qkv);
    cudaGetSymbolAddress(&p_att, g_att);

    const int attn_smem = (128 * QS_S * 2 + 128 * VS_S + 128 * PP_S) * (int)sizeof(uint32_t);
    static bool attr_set = false;
    if (!attr_set) {
        cudaFuncSetAttribute(attn_mma, cudaFuncAttributeMaxDynamicSharedMemorySize, attn_smem);
        attr_set = true;
    }

    // 1) QKV = hs @ qkv_w + qkv_b        (4096 x 2304 x 768)
    gemm_tf32<<<dim3(3 * DMODEL / 128, N_TOK / 128), 256>>>(
        hs, qkv_w, qkv_b, (float*)p_qkv, N_TOK, 3 * DMODEL, DMODEL);

    // 2) RoPE + scale + split to [h][n][d] (tf32-rounded)
    rope_split<<<(N_TOK * NH * HD + 255) / 256, 256>>>(cosp, sinp);

    // 3) Flash attention (tf32 mma)
    attn_mma<<<dim3(N_TOK / 128, NH), 256, attn_smem>>>();

    // 4) out = att @ proj_w + proj_b     (4096 x 768 x 768)
    gemm_tf32<<<dim3(DMODEL / 128, N_TOK / 128), 256>>>(
        (const float*)p_att, proj_w, proj_b, out, N_TOK, DMODEL, DMODEL);
}

// round 3
// speedup vs baseline: 3.8119x; 1.3629x over previous
#include <cuda_runtime.h>
#include <cstdint>

#define N_TOK 4096
#define NH 12
#define HD 64
#define DMODEL 768
#define QK_SCALE 0.125f
#define LOG2E 1.4426950408889634f

// Scratch (device globals: allocation-free per harness rules)
__device__ float g_qkv[(size_t)N_TOK * 3 * DMODEL];   // raw qkv (fp32)
__device__ float g_q[(size_t)NH * N_TOK * HD];        // [h][n][d], rope'd, *scale*log2e, tf32
__device__ float g_k[(size_t)NH * N_TOK * HD];        // [h][n][d], rope'd, tf32
__device__ float g_v[(size_t)NH * N_TOK * HD];        // [h][n][d], tf32
__device__ float g_att[(size_t)N_TOK * DMODEL];       // attention output [n][h*HD+d] (fp32)

// ---------------------------------------------------------------------------
// helpers
// ---------------------------------------------------------------------------
__device__ __forceinline__ uint32_t f2tf(float f) {
    uint32_t u;
    asm("cvt.rna.tf32.f32 %0, %1;" : "=r"(u) : "f"(f));
    return u;
}
__device__ __forceinline__ float ex2(float x) {
    float y;
    asm("ex2.approx.f32 %0, %1;" : "=f"(y) : "f"(x));
    return y;
}
__device__ __forceinline__ void mma_tf32(float& c0, float& c1, float& c2, float& c3,
                                         uint32_t a0, uint32_t a1, uint32_t a2, uint32_t a3,
                                         uint32_t b0, uint32_t b1) {
    asm volatile(
        "mma.sync.aligned.m16n8k8.row.col.f32.tf32.tf32.f32 "
        "{%0,%1,%2,%3}, {%4,%5,%6,%7}, {%8,%9}, {%0,%1,%2,%3};\n"
        : "+f"(c0), "+f"(c1), "+f"(c2), "+f"(c3)
        : "r"(a0), "r"(a1), "r"(a2), "r"(a3), "r"(b0), "r"(b1));
}
__device__ __forceinline__ void cp16(uint32_t dst, const void* src) {
    asm volatile("cp.async.cg.shared.global [%0], [%1], 16;" :: "r"(dst), "l"(src));
}
#define CP_COMMIT() asm volatile("cp.async.commit_group;")
#define CP_WAIT(n)  asm volatile("cp.async.wait_group %0;" :: "n"(n))

// ---------------------------------------------------------------------------
// tf32 GEMM: C[M,Nc] = A[M,K] @ B[K,Nc] + bias.  128x128x32 tiles, 256 thr.
// Warp grid 2x4, warp tile 64x32 (4 m-tiles x 4 n-tiles of m16n8k8).
// ---------------------------------------------------------------------------
#define AS_S 36
#define BS_S 136

__global__ void __launch_bounds__(256, 2) gemm_tf32(
    const float* __restrict__ A, const float* __restrict__ B,
    const float* __restrict__ bias, float* __restrict__ C,
    int M, int Nc, int K)
{
    __shared__ uint32_t As[128 * AS_S];   // [row][k]
    __shared__ uint32_t Bs[32 * BS_S];    // [k][n]

    const int tid = threadIdx.x;
    const int lane = tid & 31;
    const int w = tid >> 5;
    const int wm = w >> 2, wn = w & 3;
    const int bx = blockIdx.x, by = blockIdx.y;

    const float* Ag = A + (size_t)(by * 128) * K;
    const float* Bg = B + bx * 128;

    float acc[4][4][4];
#pragma unroll
    for (int mt = 0; mt < 4; mt++)
#pragma unroll
        for (int nt = 0; nt < 4; nt++)
#pragma unroll
            for (int c = 0; c < 4; c++) acc[mt][nt][c] = 0.f;

    for (int k0 = 0; k0 < K; k0 += 32) {
#pragma unroll
        for (int i = 0; i < 4; i++) {
            int id = tid + i * 256;
            int r = id >> 3, c = (id & 7) * 4;
            float4 v = *(const float4*)(Ag + (size_t)r * K + k0 + c);
            uint4 u = make_uint4(f2tf(v.x), f2tf(v.y), f2tf(v.z), f2tf(v.w));
            *(uint4*)&As[r * AS_S + c] = u;
        }
#pragma unroll
        for (int i = 0; i < 4; i++) {
            int id = tid + i * 256;
            int r = id >> 5, c = (id & 31) * 4;
            float4 v = *(const float4*)(Bg + (size_t)(k0 + r) * Nc + c);
            uint4 u = make_uint4(f2tf(v.x), f2tf(v.y), f2tf(v.z), f2tf(v.w));
            *(uint4*)&Bs[r * BS_S + c] = u;
        }
        __syncthreads();

#pragma unroll
        for (int ks = 0; ks < 4; ks++) {
            const int kk = ks * 8 + (lane & 3);
            uint32_t a[4][4], b[4][2];
#pragma unroll
            for (int mt = 0; mt < 4; mt++) {
                int r = wm * 64 + mt * 16 + (lane >> 2);
                a[mt][0] = As[r * AS_S + kk];
                a[mt][1] = As[(r + 8) * AS_S + kk];
                a[mt][2] = As[r * AS_S + kk + 4];
                a[mt][3] = As[(r + 8) * AS_S + kk + 4];
            }
#pragma unroll
            for (int nt = 0; nt < 4; nt++) {
                int cn = wn * 32 + nt * 8 + (lane >> 2);
                b[nt][0] = Bs[kk * BS_S + cn];
                b[nt][1] = Bs[(kk + 4) * BS_S + cn];
            }
#pragma unroll
            for (int mt = 0; mt < 4; mt++)
#pragma unroll
                for (int nt = 0; nt < 4; nt++)
                    mma_tf32(acc[mt][nt][0], acc[mt][nt][1], acc[mt][nt][2], acc[mt][nt][3],
                             a[mt][0], a[mt][1], a[mt][2], a[mt][3],
                             b[nt][0], b[nt][1]);
        }
        __syncthreads();
    }

#pragma unroll
    for (int mt = 0; mt < 4; mt++) {
#pragma unroll
        for (int nt = 0; nt < 4; nt++) {
            int r = by * 128 + wm * 64 + mt * 16 + (lane >> 2);
            int cn = bx * 128 + wn * 32 + nt * 8 + 2 * (lane & 3);
            float b0 = bias[cn], b1 = bias[cn + 1];
            float2 v0 = make_float2(acc[mt][nt][0] + b0, acc[mt][nt][1] + b1);
            float2 v1 = make_float2(acc[mt][nt][2] + b0, acc[mt][nt][3] + b1);
            *(float2*)(C + (size_t)r * Nc + cn) = v0;
            *(float2*)(C + (size_t)(r + 8) * Nc + cn) = v1;
        }
    }
}

// ---------------------------------------------------------------------------
// RoPE + scale + split into [h][n][d]; q gets QK_SCALE*LOG2E (log2-domain softmax)
// ---------------------------------------------------------------------------
__global__ void __launch_bounds__(256) rope_split(const float* __restrict__ cosp,
                                                  const float* __restrict__ sinp)
{
    int idx = blockIdx.x * 256 + threadIdx.x;
    if (idx >= N_TOK * NH * HD) return;
    int d = idx & 63;
    int h = (idx >> 6) % NH;
    int n = idx / (NH * HD);

    float c = cosp[n * HD + d];
    float s = sinp[n * HD + d];
    const float* base = g_qkv + (size_t)n * (3 * DMODEL) + h * HD;
    float qv = base[d];
    float kv = base[DMODEL + d];
    float vv = base[2 * DMODEL + d];
    int dp = (d < 32) ? d + 32 : d - 32;
    float sgn = (d < 32) ? -1.f : 1.f;
    float qr = sgn * base[dp];
    float kr = sgn * base[DMODEL + dp];

    size_t o = ((size_t)h * N_TOK + n) * HD + d;
    g_q[o] = __uint_as_float(f2tf((qv * c + qr * s) * (QK_SCALE * LOG2E)));
    g_k[o] = __uint_as_float(f2tf(kv * c + kr * s));
    g_v[o] = __uint_as_float(f2tf(vv));
}

// ---------------------------------------------------------------------------
// Flash attention, tf32 mma, cp.async double-buffered 64-key tiles.
// Grid (N/128, H), 256 thr = 8 warps; warp owns q-rows 16w..16w+15.
// S C-frags -> PV A-frags via intra-quad shuffles (no P smem).
// 2 CTAs/SM (smem 104KB, regs capped at 128).
// ---------------------------------------------------------------------------
#define KT 64                 // key tile
#define NTILES (N_TOK / KT)   // 64
#define QS_S 68
#define KS_S 68
#define VS_S 72

__global__ void __launch_bounds__(256, 2) attn_mma()
{
    extern __shared__ uint32_t sm[];
    uint32_t* Qs = sm;                          // [128][QS_S]
    uint32_t* Ks = Qs + 128 * QS_S;             // [2][KT][KS_S]
    uint32_t* Vs = Ks + 2 * KT * KS_S;          // [2][KT][VS_S]

    const int h = blockIdx.y;
    const int qb = blockIdx.x;
    const int tid = threadIdx.x;
    const int lane = tid & 31;
    const int w = tid >> 5;

    const float* qg = g_q + ((size_t)h * N_TOK + (size_t)qb * 128) * HD;
    const float* kg = g_k + (size_t)h * N_TOK * HD;
    const float* vg = g_v + (size_t)h * N_TOK * HD;

    const uint32_t ks_u32 = (uint32_t)__cvta_generic_to_shared(Ks);
    const uint32_t vs_u32 = (uint32_t)__cvta_generic_to_shared(Vs);

    // load Q tile (values already tf32-rounded)
#pragma unroll
    for (int i = 0; i < 8; i++) {
        int id = tid + i * 256;
        int r = id >> 4, c = (id & 15) * 4;
        float4 v = *(const float4*)(qg + r * HD + c);
        *(uint4*)&Qs[r * QS_S + c] = make_uint4(
            __float_as_uint(v.x), __float_as_uint(v.y),
            __float_as_uint(v.z), __float_as_uint(v.w));
    }

    // prefetch key tiles 0 and 1
#pragma unroll
    for (int t = 0; t < 2; t++) {
        const float* kt = kg + (size_t)t * KT * HD;
        const float* vt = vg + (size_t)t * KT * HD;
#pragma unroll
        for (int i = 0; i < 4; i++) {
            int id = tid + i * 256;
            int r = id >> 4, c = (id & 15) * 4;
            cp16(ks_u32 + (uint32_t)(t * KT * KS_S + r * KS_S + c) * 4, kt + r * HD + c);
            cp16(vs_u32 + (uint32_t)(t * KT * VS_S + r * VS_S + c) * 4, vt + r * HD + c);
        }
        CP_COMMIT();
    }

    float o[8][4];
#pragma unroll
    for (int nt = 0; nt < 8; nt++)
#pragma unroll
        for (int c = 0; c < 4; c++) o[nt][c] = 0.f;
    float m0 = -1e30f, m1 = -1e30f, l0 = 0.f, l1 = 0.f;

    const int qrow = w * 16 + (lane >> 2);
    const int q4 = lane & 3;
    const int srcA = (lane & ~3) | (q4 >> 1);
    const int srcB = srcA + 2;
    const bool odd = q4 & 1;

    for (int t = 0; t < NTILES; t++) {
        CP_WAIT(1);
        __syncthreads();
        const uint32_t* Kb = Ks + (t & 1) * KT * KS_S;
        const uint32_t* Vb = Vs + (t & 1) * KT * VS_S;

        // ---- S = Q K^T : 8 n-tiles over 64 keys
        float s[8][4];
#pragma unroll
        for (int nt = 0; nt < 8; nt++)
#pragma unroll
            for (int c = 0; c < 4; c++) s[nt][c] = 0.f;

#pragma unroll
        for (int ks = 0; ks < 8; ks++) {
            const int kk = ks * 8 + q4;
            uint32_t a0 = Qs[qrow * QS_S + kk];
            uint32_t a1 = Qs[(qrow + 8) * QS_S + kk];
            uint32_t a2 = Qs[qrow * QS_S + kk + 4];
            uint32_t a3 = Qs[(qrow + 8) * QS_S + kk + 4];
#pragma unroll
            for (int nt = 0; nt < 8; nt++) {
                int nn = nt * 8 + (lane >> 2);
                uint32_t b0 = Kb[nn * KS_S + kk];
                uint32_t b1 = Kb[nn * KS_S + kk + 4];
                mma_tf32(s[nt][0], s[nt][1], s[nt][2], s[nt][3],
                         a0, a1, a2, a3, b0, b1);
            }
        }

        // ---- online softmax (log2 domain; warp-local rows qrow, qrow+8)
        {
            float mt = -1e30f;
#pragma unroll
            for (int nt = 0; nt < 8; nt++)
                mt = fmaxf(mt, fmaxf(s[nt][0], s[nt][1]));
            mt = fmaxf(mt, __shfl_xor_sync(0xffffffffu, mt, 1));
            mt = fmaxf(mt, __shfl_xor_sync(0xffffffffu, mt, 2));
            float nm = fmaxf(m0, mt);
            float al = ex2(m0 - nm);
            m0 = nm;
            float rs = 0.f;
#pragma unroll
            for (int nt = 0; nt < 8; nt++) {
                s[nt][0] = ex2(s[nt][0] - nm);
                s[nt][1] = ex2(s[nt][1] - nm);
                rs += s[nt][0] + s[nt][1];
            }
            rs += __shfl_xor_sync(0xffffffffu, rs, 1);
            rs += __shfl_xor_sync(0xffffffffu, rs, 2);
            l0 = l0 * al + rs;
#pragma unroll
            for (int nt = 0; nt < 8; nt++) { o[nt][0] *= al; o[nt][1] *= al; }
        }
        {
            float mt = -1e30f;
#pragma unroll
            for (int nt = 0; nt < 8; nt++)
                mt = fmaxf(mt, fmaxf(s[nt][2], s[nt][3]));
            mt = fmaxf(mt, __shfl_xor_sync(0xffffffffu, mt, 1));
            mt = fmaxf(mt, __shfl_xor_sync(0xffffffffu, mt, 2));
            float nm = fmaxf(m1, mt);
            float al = ex2(m1 - nm);
            m1 = nm;
            float rs = 0.f;
#pragma unroll
            for (int nt = 0; nt < 8; nt++) {
                s[nt][2] = ex2(s[nt][2] - nm);
                s[nt][3] = ex2(s[nt][3] - nm);
                rs += s[nt][2] + s[nt][3];
            }
            rs += __shfl_xor_sync(0xffffffffu, rs, 1);
            rs += __shfl_xor_sync(0xffffffffu, rs, 2);
            l1 = l1 * al + rs;
#pragma unroll
            for (int nt = 0; nt < 8; nt++) { o[nt][2] *= al; o[nt][3] *= al; }
        }

        // ---- O += P V : C-frag -> A-frag via intra-quad shuffles
#pragma unroll
        for (int ks = 0; ks < 8; ks++) {
            float c0A = __shfl_sync(0xffffffffu, s[ks][0], srcA);
            float c1A = __shfl_sync(0xffffffffu, s[ks][1], srcA);
            float c0B = __shfl_sync(0xffffffffu, s[ks][0], srcB);
            float c1B = __shfl_sync(0xffffffffu, s[ks][1], srcB);
            float c2A = __shfl_sync(0xffffffffu, s[ks][2], srcA);
            float c3A = __shfl_sync(0xffffffffu, s[ks][3], srcA);
            float c2B = __shfl_sync(0xffffffffu, s[ks][2], srcB);
            float c3B = __shfl_sync(0xffffffffu, s[ks][3], srcB);
            uint32_t a0 = f2tf(odd ? c1A : c0A);   // row qrow,   col q
            uint32_t a1 = f2tf(odd ? c3A : c2A);   // row qrow+8, col q
            uint32_t a2 = f2tf(odd ? c1B : c0B);   // row qrow,   col q+4
            uint32_t a3 = f2tf(odd ? c3B : c2B);   // row qrow+8, col q+4
            const int kk = ks * 8 + q4;
#pragma unroll
            for (int nt = 0; nt < 8; nt++) {
                int dd = nt * 8 + (lane >> 2);
                uint32_t b0 = Vb[kk * VS_S + dd];
                uint32_t b1 = Vb[(kk + 4) * VS_S + dd];
                mma_tf32(o[nt][0], o[nt][1], o[nt][2], o[nt][3],
                         a0, a1, a2, a3, b0, b1);
            }
        }

        __syncthreads();   // all warps done with buf (t&1) before overwrite
        if (t + 2 < NTILES) {
            int tn = t + 2;
            const float* kt = kg + (size_t)tn * KT * HD;
            const float* vt = vg + (size_t)tn * KT * HD;
            int buf = tn & 1;
#pragma unroll
            for (int i = 0; i < 4; i++) {
                int id = tid + i * 256;
                int r = id >> 4, c = (id & 15) * 4;
                cp16(ks_u32 + (uint32_t)(buf * KT * KS_S + r * KS_S + c) * 4, kt + r * HD + c);
                cp16(vs_u32 + (uint32_t)(buf * KT * VS_S + r * VS_S + c) * 4, vt + r * HD + c);
            }
        }
        CP_COMMIT();       // uniform group count (empty group near the end)
    }

    // ---- normalize + write [n][h*HD+d]
    float inv0 = 1.f / l0, inv1 = 1.f / l1;
    int row0 = qb * 128 + qrow;
#pragma unroll
    for (int nt = 0; nt < 8; nt++) {
        int dd = h * HD + nt * 8 + 2 * q4;
        float2 v0 = make_float2(o[nt][0] * inv0, o[nt][1] * inv0);
        float2 v1 = make_float2(o[nt][2] * inv1, o[nt][3] * inv1);
        *(float2*)(g_att + (size_t)row0 * DMODEL + dd) = v0;
        *(float2*)(g_att + (size_t)(row0 + 8) * DMODEL + dd) = v1;
    }
}

// ---------------------------------------------------------------------------
extern "C" void kernel_launch(void* const* d_in, const int* in_sizes, int n_in,
                              void* d_out, int out_size)
{
    (void)in_sizes; (void)n_in; (void)out_size;
    const float* hs     = (const float*)d_in[0];
    const float* cosp   = (const float*)d_in[1];
    const float* sinp   = (const float*)d_in[2];
    const float* qkv_w  = (const float*)d_in[3];
    const float* qkv_b  = (const float*)d_in[4];
    const float* proj_w = (const float*)d_in[5];
    const float* proj_b = (const float*)d_in[6];
    float* out = (float*)d_out;

    void *p_qkv = nullptr, *p_att = nullptr;
    cudaGetSymbolAddress(&p_qkv, g_qkv);
    cudaGetSymbolAddress(&p_att, g_att);

    const int attn_smem = (128 * QS_S + 2 * KT * KS_S + 2 * KT * VS_S) * (int)sizeof(uint32_t);
    static bool attr_set = false;
    if (!attr_set) {
        cudaFuncSetAttribute(attn_mma, cudaFuncAttributeMaxDynamicSharedMemorySize, attn_smem);
        attr_set = true;
    }

    // 1) QKV = hs @ qkv_w + qkv_b        (4096 x 2304 x 768)
    gemm_tf32<<<dim3(3 * DMODEL / 128, N_TOK / 128), 256>>>(
        hs, qkv_w, qkv_b, (float*)p_qkv, N_TOK, 3 * DMODEL, DMODEL);

    // 2) RoPE + scale(*log2e) + split to [h][n][d] (tf32-rounded)
    rope_split<<<(N_TOK * NH * HD + 255) / 256, 256>>>(cosp, sinp);

    // 3) Flash attention (tf32 mma, cp.async pipeline)
    attn_mma<<<dim3(N_TOK / 128, NH), 256, attn_smem>>>();

    // 4) out = att @ proj_w + proj_b     (4096 x 768 x 768)
    gemm_tf32<<<dim3(DMODEL / 128, N_TOK / 128), 256>>>(
        (const float*)p_att, proj_w, proj_b, out, N_TOK, DMODEL, DMODEL);
}

// round 4
// speedup vs baseline: 4.2192x; 1.1068x over previous
#include <cuda_runtime.h>
#include <cstdint>

#define N_TOK 4096
#define NH 12
#define HD 64
#define DMODEL 768
#define QK_SCALE 0.125f
#define LOG2E 1.4426950408889634f

// Scratch (device globals: allocation-free per harness rules)
__device__ float g_qkv[(size_t)N_TOK * 3 * DMODEL];   // raw qkv (fp32)
__device__ float g_q[(size_t)NH * N_TOK * HD];        // [h][n][d'] d-permuted, *scale*log2e, tf32
__device__ float g_k[(size_t)NH * N_TOK * HD];        // [h][n][d'] d-permuted, tf32
__device__ float g_vt[(size_t)NH * HD * N_TOK];       // [h][d][n'] key-permuted V^T, tf32
__device__ float g_att[(size_t)N_TOK * DMODEL];       // attention out [n][h*HD+d], tf32-rounded
__device__ float g_hs[(size_t)N_TOK * DMODEL];        // tf32-rounded hidden_states
__device__ float g_w1[(size_t)DMODEL * 3 * DMODEL];   // tf32-rounded qkv_w
__device__ float g_w2[(size_t)DMODEL * DMODEL];       // tf32-rounded proj_w

// ---------------------------------------------------------------------------
// helpers
// ---------------------------------------------------------------------------
__device__ __forceinline__ uint32_t f2tf(float f) {
    uint32_t u;
    asm("cvt.rna.tf32.f32 %0, %1;" : "=r"(u) : "f"(f));
    return u;
}
__device__ __forceinline__ float ex2(float x) {
    float y;
    asm("ex2.approx.f32 %0, %1;" : "=f"(y) : "f"(x));
    return y;
}
__device__ __forceinline__ void mma_tf32(float& c0, float& c1, float& c2, float& c3,
                                         uint32_t a0, uint32_t a1, uint32_t a2, uint32_t a3,
                                         uint32_t b0, uint32_t b1) {
    asm volatile(
        "mma.sync.aligned.m16n8k8.row.col.f32.tf32.tf32.f32 "
        "{%0,%1,%2,%3}, {%4,%5,%6,%7}, {%8,%9}, {%0,%1,%2,%3};\n"
        : "+f"(c0), "+f"(c1), "+f"(c2), "+f"(c3)
        : "r"(a0), "r"(a1), "r"(a2), "r"(a3), "r"(b0), "r"(b1));
}
__device__ __forceinline__ void cp16(uint32_t dst, const void* src) {
    asm volatile("cp.async.cg.shared.global [%0], [%1], 16;" :: "r"(dst), "l"(src));
}
#define CP_COMMIT() asm volatile("cp.async.commit_group;")
#define CP_WAIT(n)  asm volatile("cp.async.wait_group %0;" :: "n"(n))

// pair-interleave permutation within each 8-group: j<4 -> 2j ; j>=4 -> 2(j-4)+1
__device__ __forceinline__ int pperm(int j) {
    int r = j & 7;
    return (j & ~7) | ((r < 4) ? (2 * r) : (2 * (r - 4) + 1));
}

// ---------------------------------------------------------------------------
// pre-round hs / qkv_w / proj_w to tf32 (lets GEMMs use raw cp.async)
// ---------------------------------------------------------------------------
#define N_HS4 (N_TOK * DMODEL / 4)
#define N_W14 (DMODEL * 3 * DMODEL / 4)
#define N_W24 (DMODEL * DMODEL / 4)

__global__ void __launch_bounds__(256) preround(const float4* __restrict__ hs,
                                                const float4* __restrict__ w1,
                                                const float4* __restrict__ w2)
{
    int i = blockIdx.x * 256 + threadIdx.x;
    float4 v; float4* dst;
    if (i < N_HS4)              { v = hs[i];               dst = (float4*)g_hs + i; }
    else if (i < N_HS4 + N_W14) { v = w1[i - N_HS4];       dst = (float4*)g_w1 + (i - N_HS4); }
    else if (i < N_HS4 + N_W14 + N_W24) {
        v = w2[i - N_HS4 - N_W14]; dst = (float4*)g_w2 + (i - N_HS4 - N_W14);
    } else return;
    float4 o = make_float4(__uint_as_float(f2tf(v.x)), __uint_as_float(f2tf(v.y)),
                           __uint_as_float(f2tf(v.z)), __uint_as_float(f2tf(v.w)));
    *dst = o;
}

// ---------------------------------------------------------------------------
// tf32 GEMM with cp.async double-buffered k-chunks.
// C[M,Nc] = A[M,K] @ B[K,Nc] + bias.  128x128x32 tiles, 256 thr, 2 CTA/SM.
// Inputs must be pre-rounded to tf32 values.
// ---------------------------------------------------------------------------
#define AS_S 36
#define BS_S 136
#define A_BUF (128 * AS_S)   // 4608
#define B_BUF (32 * BS_S)    // 4352
#define GEMM_SMEM ((2 * A_BUF + 2 * B_BUF) * 4)

__global__ void __launch_bounds__(256, 2) gemm_tf32(
    const float* __restrict__ A, const float* __restrict__ B,
    const float* __restrict__ bias, float* __restrict__ C,
    int M, int Nc, int K)
{
    extern __shared__ uint32_t smg[];
    uint32_t* As = smg;                // [2][128][AS_S]
    uint32_t* Bs = smg + 2 * A_BUF;    // [2][32][BS_S]

    const int tid = threadIdx.x;
    const int lane = tid & 31;
    const int w = tid >> 5;
    const int wm = w >> 2, wn = w & 3;
    const int bx = blockIdx.x, by = blockIdx.y;

    const float* Ag = A + (size_t)(by * 128) * K;
    const float* Bg = B + bx * 128;

    const uint32_t as_u = (uint32_t)__cvta_generic_to_shared(As);
    const uint32_t bs_u = (uint32_t)__cvta_generic_to_shared(Bs);

    float acc[4][4][4];
#pragma unroll
    for (int mt = 0; mt < 4; mt++)
#pragma unroll
        for (int nt = 0; nt < 4; nt++)
#pragma unroll
            for (int c = 0; c < 4; c++) acc[mt][nt][c] = 0.f;

    const int NC = K / 32;

    // prefetch chunk 0 into buf 0
#pragma unroll
    for (int i = 0; i < 4; i++) {
        int id = tid + i * 256;
        int r = id >> 3, c = (id & 7) * 4;
        cp16(as_u + (uint32_t)(r * AS_S + c) * 4, Ag + (size_t)r * K + c);
    }
#pragma unroll
    for (int i = 0; i < 4; i++) {
        int id = tid + i * 256;
        int r = id >> 5, c = (id & 31) * 4;
        cp16(bs_u + (uint32_t)(r * BS_S + c) * 4, Bg + (size_t)r * Nc + c);
    }
    CP_COMMIT();

    for (int ch = 0; ch < NC; ch++) {
        if (ch + 1 < NC) {
            int k0 = (ch + 1) * 32;
            int buf = (ch + 1) & 1;
#pragma unroll
            for (int i = 0; i < 4; i++) {
                int id = tid + i * 256;
                int r = id >> 3, c = (id & 7) * 4;
                cp16(as_u + (uint32_t)(buf * A_BUF + r * AS_S + c) * 4,
                     Ag + (size_t)r * K + k0 + c);
            }
#pragma unroll
            for (int i = 0; i < 4; i++) {
                int id = tid + i * 256;
                int r = id >> 5, c = (id & 31) * 4;
                cp16(bs_u + (uint32_t)(buf * B_BUF + r * BS_S + c) * 4,
                     Bg + (size_t)(k0 + r) * Nc + c);
            }
        }
        CP_COMMIT();
        CP_WAIT(1);
        __syncthreads();

        const uint32_t* Ab = As + (ch & 1) * A_BUF;
        const uint32_t* Bb = Bs + (ch & 1) * B_BUF;

#pragma unroll
        for (int ks = 0; ks < 4; ks++) {
            const int kk = ks * 8 + (lane & 3);
            uint32_t a[4][4], b[4][2];
#pragma unroll
            for (int mt = 0; mt < 4; mt++) {
                int r = wm * 64 + mt * 16 + (lane >> 2);
                a[mt][0] = Ab[r * AS_S + kk];
                a[mt][1] = Ab[(r + 8) * AS_S + kk];
                a[mt][2] = Ab[r * AS_S + kk + 4];
                a[mt][3] = Ab[(r + 8) * AS_S + kk + 4];
            }
#pragma unroll
            for (int nt = 0; nt < 4; nt++) {
                int cn = wn * 32 + nt * 8 + (lane >> 2);
                b[nt][0] = Bb[kk * BS_S + cn];
                b[nt][1] = Bb[(kk + 4) * BS_S + cn];
            }
#pragma unroll
            for (int mt = 0; mt < 4; mt++)
#pragma unroll
                for (int nt = 0; nt < 4; nt++)
                    mma_tf32(acc[mt][nt][0], acc[mt][nt][1], acc[mt][nt][2], acc[mt][nt][3],
                             a[mt][0], a[mt][1], a[mt][2], a[mt][3],
                             b[nt][0], b[nt][1]);
        }
        __syncthreads();
    }

#pragma unroll
    for (int mt = 0; mt < 4; mt++) {
#pragma unroll
        for (int nt = 0; nt < 4; nt++) {
            int r = by * 128 + wm * 64 + mt * 16 + (lane >> 2);
            int cn = bx * 128 + wn * 32 + nt * 8 + 2 * (lane & 3);
            float b0 = bias[cn], b1 = bias[cn + 1];
            float2 v0 = make_float2(acc[mt][nt][0] + b0, acc[mt][nt][1] + b1);
            float2 v1 = make_float2(acc[mt][nt][2] + b0, acc[mt][nt][3] + b1);
            *(float2*)(C + (size_t)r * Nc + cn) = v0;
            *(float2*)(C + (size_t)(r + 8) * Nc + cn) = v1;
        }
    }
}

// ---------------------------------------------------------------------------
// RoPE + scale + split q/k into [h][n][d'] with pair-interleaved d (tf32)
// ---------------------------------------------------------------------------
__global__ void __launch_bounds__(256) rope_split(const float* __restrict__ cosp,
                                                  const float* __restrict__ sinp)
{
    int idx = blockIdx.x * 256 + threadIdx.x;
    if (idx >= N_TOK * NH * HD) return;
    int d = idx & 63;
    int h = (idx >> 6) % NH;
    int n = idx / (NH * HD);

    float c = cosp[n * HD + d];
    float s = sinp[n * HD + d];
    const float* base = g_qkv + (size_t)n * (3 * DMODEL) + h * HD;
    float qv = base[d];
    float kv = base[DMODEL + d];
    int dp = (d < 32) ? d + 32 : d - 32;
    float sgn = (d < 32) ? -1.f : 1.f;
    float qr = sgn * base[dp];
    float kr = sgn * base[DMODEL + dp];

    size_t o = ((size_t)h * N_TOK + n) * HD + pperm(d);
    g_q[o] = __uint_as_float(f2tf((qv * c + qr * s) * (QK_SCALE * LOG2E)));
    g_k[o] = __uint_as_float(f2tf(kv * c + kr * s));
}

// ---------------------------------------------------------------------------
// V transpose: g_qkv v-part [n][h*64+d] -> g_vt [h][d][perm(n)] (tf32)
// 64x64 tiles through smem; coalesced both sides.
// ---------------------------------------------------------------------------
__global__ void __launch_bounds__(256) v_transpose()
{
    __shared__ float sm[64 * 65];
    const int h = blockIdx.y;
    const int nb = blockIdx.x;
    const int tid = threadIdx.x;

#pragma unroll
    for (int i = 0; i < 16; i++) {
        int idx = tid + i * 256;
        int nl = idx >> 6, d = idx & 63;
        sm[nl * 65 + d] = g_qkv[(size_t)(nb * 64 + nl) * (3 * DMODEL) + 2 * DMODEL + h * HD + d];
    }
    __syncthreads();
#pragma unroll
    for (int i = 0; i < 16; i++) {
        int idx = tid + i * 256;
        int d = idx >> 6, nl = idx & 63;
        float v = sm[nl * 65 + d];
        g_vt[((size_t)(h * HD + d)) * N_TOK + nb * 64 + pperm(nl)] =
            __uint_as_float(f2tf(v));
    }
}

// ---------------------------------------------------------------------------
// Flash attention, tf32 mma, LDS.64 fragments via permuted layouts,
// cp.async double-buffered 64-key tiles. 2 CTAs/SM.
// ---------------------------------------------------------------------------
#define KT 64
#define NTILES (N_TOK / KT)
#define ST 72   // shared stride: banks 8r+2q -> conflict-free LDS.64
#define ATTN_SMEM ((128 * ST + 2 * KT * ST + 2 * KT * ST) * 4)

__global__ void __launch_bounds__(256, 2) attn_mma()
{
    extern __shared__ uint32_t sm[];
    uint32_t* Qs = sm;                   // [128][ST]
    uint32_t* Ks = Qs + 128 * ST;        // [2][KT keys][ST]  (d' cols)
    uint32_t* Vs = Ks + 2 * KT * ST;     // [2][HD d][ST]     (key' cols, V^T)

    const int h = blockIdx.y;
    const int qb = blockIdx.x;
    const int tid = threadIdx.x;
    const int lane = tid & 31;
    const int w = tid >> 5;

    const float* qg = g_q + ((size_t)h * N_TOK + (size_t)qb * 128) * HD;
    const float* kg = g_k + (size_t)h * N_TOK * HD;
    const float* vtg = g_vt + (size_t)h * HD * N_TOK;

    const uint32_t ks_u32 = (uint32_t)__cvta_generic_to_shared(Ks);
    const uint32_t vs_u32 = (uint32_t)__cvta_generic_to_shared(Vs);

    // load Q tile (pre-rounded, d-permuted)
#pragma unroll
    for (int i = 0; i < 8; i++) {
        int id = tid + i * 256;
        int r = id >> 4, c = (id & 15) * 4;
        *(uint4*)&Qs[r * ST + c] = *(const uint4*)(qg + r * HD + c);
    }

    // prefetch key tiles 0 and 1
#pragma unroll
    for (int t = 0; t < 2; t++) {
        const float* kt = kg + (size_t)t * KT * HD;
#pragma unroll
        for (int i = 0; i < 4; i++) {
            int id = tid + i * 256;
            int r = id >> 4, c = (id & 15) * 4;
            cp16(ks_u32 + (uint32_t)(t * KT * ST + r * ST + c) * 4, kt + r * HD + c);
            // V^T rows: d = r, key cols from global row (h,d)
            cp16(vs_u32 + (uint32_t)(t * KT * ST + r * ST + c) * 4,
                 vtg + (size_t)r * N_TOK + t * KT + c);
        }
        CP_COMMIT();
    }

    float o[8][4];
#pragma unroll
    for (int nt = 0; nt < 8; nt++)
#pragma unroll
        for (int c = 0; c < 4; c++) o[nt][c] = 0.f;
    float m0 = -1e30f, m1 = -1e30f, l0 = 0.f, l1 = 0.f;

    const int qrow = w * 16 + (lane >> 2);
    const int q4 = lane & 3;
    const int srcA = (lane & ~3) | (q4 >> 1);
    const int srcB = srcA + 2;
    const bool odd = q4 & 1;

    for (int t = 0; t < NTILES; t++) {
        CP_WAIT(1);
        __syncthreads();
        const uint32_t* Kb = Ks + (t & 1) * KT * ST;
        const uint32_t* Vb = Vs + (t & 1) * KT * ST;

        // ---- S = Q K^T : 8 n-tiles over 64 keys (LDS.64 frags)
        float s[8][4];
#pragma unroll
        for (int nt = 0; nt < 8; nt++)
#pragma unroll
            for (int c = 0; c < 4; c++) s[nt][c] = 0.f;

#pragma unroll
        for (int ks = 0; ks < 8; ks++) {
            const int kc = ks * 8 + 2 * q4;      // permuted pos of (kk, kk+4)
            uint2 aA = *(const uint2*)&Qs[qrow * ST + kc];
            uint2 aB = *(const uint2*)&Qs[(qrow + 8) * ST + kc];
#pragma unroll
            for (int nt = 0; nt < 8; nt++) {
                int nn = nt * 8 + (lane >> 2);
                uint2 b = *(const uint2*)&Kb[nn * ST + kc];
                mma_tf32(s[nt][0], s[nt][1], s[nt][2], s[nt][3],
                         aA.x, aB.x, aA.y, aB.y, b.x, b.y);
            }
        }

        // ---- online softmax (log2 domain; warp-local rows qrow, qrow+8)
        {
            float mt = -1e30f;
#pragma unroll
            for (int nt = 0; nt < 8; nt++)
                mt = fmaxf(mt, fmaxf(s[nt][0], s[nt][1]));
            mt = fmaxf(mt, __shfl_xor_sync(0xffffffffu, mt, 1));
            mt = fmaxf(mt, __shfl_xor_sync(0xffffffffu, mt, 2));
            float nm = fmaxf(m0, mt);
            float al = ex2(m0 - nm);
            m0 = nm;
            float rs = 0.f;
#pragma unroll
            for (int nt = 0; nt < 8; nt++) {
                s[nt][0] = ex2(s[nt][0] - nm);
                s[nt][1] = ex2(s[nt][1] - nm);
                rs += s[nt][0] + s[nt][1];
            }
            rs += __shfl_xor_sync(0xffffffffu, rs, 1);
            rs += __shfl_xor_sync(0xffffffffu, rs, 2);
            l0 = l0 * al + rs;
#pragma unroll
            for (int nt = 0; nt < 8; nt++) { o[nt][0] *= al; o[nt][1] *= al; }
        }
        {
            float mt = -1e30f;
#pragma unroll
            for (int nt = 0; nt < 8; nt++)
                mt = fmaxf(mt, fmaxf(s[nt][2], s[nt][3]));
            mt = fmaxf(mt, __shfl_xor_sync(0xffffffffu, mt, 1));
            mt = fmaxf(mt, __shfl_xor_sync(0xffffffffu, mt, 2));
            float nm = fmaxf(m1, mt);
            float al = ex2(m1 - nm);
            m1 = nm;
            float rs = 0.f;
#pragma unroll
            for (int nt = 0; nt < 8; nt++) {
                s[nt][2] = ex2(s[nt][2] - nm);
                s[nt][3] = ex2(s[nt][3] - nm);
                rs += s[nt][2] + s[nt][3];
            }
            rs += __shfl_xor_sync(0xffffffffu, rs, 1);
            rs += __shfl_xor_sync(0xffffffffu, rs, 2);
            l1 = l1 * al + rs;
#pragma unroll
            for (int nt = 0; nt < 8; nt++) { o[nt][2] *= al; o[nt][3] *= al; }
        }

        // ---- O += P V : C-frag -> A-frag via intra-quad shuffles; V^T LDS.64
#pragma unroll
        for (int ks = 0; ks < 8; ks++) {
            float c0A = __shfl_sync(0xffffffffu, s[ks][0], srcA);
            float c1A = __shfl_sync(0xffffffffu, s[ks][1], srcA);
            float c0B = __shfl_sync(0xffffffffu, s[ks][0], srcB);
            float c1B = __shfl_sync(0xffffffffu, s[ks][1], srcB);
            float c2A = __shfl_sync(0xffffffffu, s[ks][2], srcA);
            float c3A = __shfl_sync(0xffffffffu, s[ks][3], srcA);
            float c2B = __shfl_sync(0xffffffffu, s[ks][2], srcB);
            float c3B = __shfl_sync(0xffffffffu, s[ks][3], srcB);
            uint32_t a0 = f2tf(odd ? c1A : c0A);
            uint32_t a1 = f2tf(odd ? c3A : c2A);
            uint32_t a2 = f2tf(odd ? c1B : c0B);
            uint32_t a3 = f2tf(odd ? c3B : c2B);
            const int kc = ks * 8 + 2 * q4;      // permuted key pos of (kk, kk+4)
#pragma unroll
            for (int nt = 0; nt < 8; nt++) {
                int dd = nt * 8 + (lane >> 2);
                uint2 b = *(const uint2*)&Vb[dd * ST + kc];
                mma_tf32(o[nt][0], o[nt][1], o[nt][2], o[nt][3],
                         a0, a1, a2, a3, b.x, b.y);
            }
        }

        __syncthreads();   // all warps done with buf (t&1) before overwrite
        if (t + 2 < NTILES) {
            int tn = t + 2;
            const float* kt = kg + (size_t)tn * KT * HD;
            int buf = tn & 1;
#pragma unroll
            for (int i = 0; i < 4; i++) {
                int id = tid + i * 256;
                int r = id >> 4, c = (id & 15) * 4;
                cp16(ks_u32 + (uint32_t)(buf * KT * ST + r * ST + c) * 4, kt + r * HD + c);
                cp16(vs_u32 + (uint32_t)(buf * KT * ST + r * ST + c) * 4,
                     vtg + (size_t)r * N_TOK + tn * KT + c);
            }
        }
        CP_COMMIT();
    }

    // ---- normalize + write [n][h*HD+d], tf32-rounded for proj GEMM
    float inv0 = 1.f / l0, inv1 = 1.f / l1;
    int row0 = qb * 128 + qrow;
#pragma unroll
    for (int nt = 0; nt < 8; nt++) {
        int dd = h * HD + nt * 8 + 2 * q4;
        float2 v0 = make_float2(__uint_as_float(f2tf(o[nt][0] * inv0)),
                                __uint_as_float(f2tf(o[nt][1] * inv0)));
        float2 v1 = make_float2(__uint_as_float(f2tf(o[nt][2] * inv1)),
                                __uint_as_float(f2tf(o[nt][3] * inv1)));
        *(float2*)(g_att + (size_t)row0 * DMODEL + dd) = v0;
        *(float2*)(g_att + (size_t)(row0 + 8) * DMODEL + dd) = v1;
    }
}

// ---------------------------------------------------------------------------
extern "C" void kernel_launch(void* const* d_in, const int* in_sizes, int n_in,
                              void* d_out, int out_size)
{
    (void)in_sizes; (void)n_in; (void)out_size;
    const float* hs     = (const float*)d_in[0];
    const float* cosp   = (const float*)d_in[1];
    const float* sinp   = (const float*)d_in[2];
    const float* qkv_w  = (const float*)d_in[3];
    const float* qkv_b  = (const float*)d_in[4];
    const float* proj_w = (const float*)d_in[5];
    const float* proj_b = (const float*)d_in[6];
    float* out = (float*)d_out;

    void *p_qkv = nullptr, *p_att = nullptr, *p_hs = nullptr, *p_w1 = nullptr, *p_w2 = nullptr;
    cudaGetSymbolAddress(&p_qkv, g_qkv);
    cudaGetSymbolAddress(&p_att, g_att);
    cudaGetSymbolAddress(&p_hs, g_hs);
    cudaGetSymbolAddress(&p_w1, g_w1);
    cudaGetSymbolAddress(&p_w2, g_w2);

    static bool attr_set = false;
    if (!attr_set) {
        cudaFuncSetAttribute(attn_mma, cudaFuncAttributeMaxDynamicSharedMemorySize, ATTN_SMEM);
        cudaFuncSetAttribute(gemm_tf32, cudaFuncAttributeMaxDynamicSharedMemorySize, GEMM_SMEM);
        attr_set = true;
    }

    // 0) pre-round hs / qkv_w / proj_w to tf32
    {
        int total4 = N_HS4 + N_W14 + N_W24;
        preround<<<(total4 + 255) / 256, 256>>>(
            (const float4*)hs, (const float4*)qkv_w, (const float4*)proj_w);
    }

    // 1) QKV = hs @ qkv_w + qkv_b        (4096 x 2304 x 768)
    gemm_tf32<<<dim3(3 * DMODEL / 128, N_TOK / 128), 256, GEMM_SMEM>>>(
        (const float*)p_hs, (const float*)p_w1, qkv_b, (float*)p_qkv,
        N_TOK, 3 * DMODEL, DMODEL);

    // 2) RoPE + scale(*log2e) + split q/k (d-permuted, tf32)
    rope_split<<<(N_TOK * NH * HD + 255) / 256, 256>>>(cosp, sinp);

    // 2b) V transpose to [h][d][perm(n)] (tf32)
    v_transpose<<<dim3(N_TOK / 64, NH), 256>>>();

    // 3) Flash attention (tf32 mma, LDS.64 frags, cp.async pipeline)
    attn_mma<<<dim3(N_TOK / 128, NH), 256, ATTN_SMEM>>>();

    // 4) out = att @ proj_w + proj_b     (4096 x 768 x 768)
    gemm_tf32<<<dim3(DMODEL / 128, N_TOK / 128), 256, GEMM_SMEM>>>(
        (const float*)p_att, (const float*)p_w2, proj_b, out,
        N_TOK, DMODEL, DMODEL);
}